// round 7
// baseline (speedup 1.0000x reference)
#include <cuda_runtime.h>
#include <cuda_bf16.h>
#include <mma.h>
#include <cstdint>
#include <cstddef>

#define NMAX 100000
#define EMAX 600000
#define NG   256
#define DH   128
#define H4   512
#define BN_EPS 1e-5f
#define GN_EPS 1e-5f

using namespace nvcuda;

// ---------------- static device scratch ----------------
static __device__ __nv_bfloat16 g_Ah[(size_t)NMAX * DH];
static __device__ __nv_bfloat16 g_Al[(size_t)NMAX * DH];
static __device__ float g_z1[(size_t)NMAX * H4];
static __device__ float g_z2[(size_t)NMAX * DH];
static __device__ float g_h [(size_t)NMAX * DH];
static __device__ __nv_bfloat16 g_W1h[4 * H4 * DH];
static __device__ __nv_bfloat16 g_W1l[4 * H4 * DH];
static __device__ __nv_bfloat16 g_W2h[4 * DH * H4];
static __device__ __nv_bfloat16 g_W2l[4 * DH * H4];
static __device__ int   g_rowptr[NMAX + 1];
static __device__ int   g_cursor[NMAX];
static __device__ int   g_colidx[EMAX];
static __device__ int   g_bsum[128];
static __device__ int   g_boff[128];
static __device__ int   g_gstart[NG + 1];
static __device__ float g_invcnt[NG];
static __device__ float g_bnstat[2 * H4];
static __device__ float g_scale[H4];
static __device__ float g_shift[H4];
static __device__ float g_GS[NG * DH];
static __device__ float g_GB[NG * DH];
static __device__ int   g_i64;

// ---------------- helpers ----------------
__device__ __forceinline__ float selu_f(float x) {
    const float lam = 1.0507009873554805f;
    const float la  = 1.7580993408473766f;
    return x > 0.f ? lam * x : la * (__expf(x) - 1.f);
}
__device__ __forceinline__ int readIdx(const void* p, long long i) {
    return g_i64 ? (int)((const long long*)p)[i] : ((const int*)p)[i];
}
__device__ __forceinline__ void split2(float a, float b, uint32_t& hi, uint32_t& lo) {
    uint32_t h;
    asm("cvt.rn.bf16x2.f32 %0, %1, %2;" : "=r"(h) : "f"(b), "f"(a));
    float fa = __uint_as_float(h << 16);
    float fb = __uint_as_float(h & 0xffff0000u);
    float ra = a - fa, rb = b - fb;
    uint32_t l;
    asm("cvt.rn.bf16x2.f32 %0, %1, %2;" : "=r"(l) : "f"(rb), "f"(ra));
    hi = h; lo = l;
}
__device__ __forceinline__ void cpa16(uint32_t dst, const void* src, int srcsz) {
    asm volatile("cp.async.cg.shared.global [%0], [%1], 16, %2;"
                 :: "r"(dst), "l"(src), "r"(srcsz));
}
#define CPA_COMMIT() asm volatile("cp.async.commit_group;" ::: "memory")
#define CPA_WAIT0()  asm volatile("cp.async.wait_group 0;" ::: "memory")
#define CPA_WAIT1()  asm volatile("cp.async.wait_group 1;" ::: "memory")

#define LDA 72
#define LDAB 144
#define LDC 132

// GEMM1 smem: two sets of {Ah(256x64),Al,Bh(128x64),Bl}
#define G1_AH 0
#define G1_AL 36864
#define G1_BH 73728
#define G1_BL 92160
#define G1_SET 110592
#define SMEM_G1 (2 * G1_SET)            // 221184

// GEMM2 smem: single split-A tile + double B + fp32 stage (stride 272B)
#define G2_TAH 0
#define G2_TAL 36864
#define G2_B0  73728
#define G2_B1  110592
#define G2_STG 147456
#define SMEM_G2 (G2_STG + 256 * 272)    // 217088

// ---------------- shared 64x64-warp MMA for one K=64 chunk ----------------
// A tiles: 256 rows; B tiles: 128 rows. Warp w: m0=(w>>1)*64, n0=(w&1)*64.
__device__ __forceinline__ void mma_chunk64(
    const char* pAh, const char* pAl, const char* pBh, const char* pBl,
    int m0, int n0,
    wmma::fragment<wmma::accumulator, 16, 16, 16, float> acc[4][4]) {
    const __nv_bfloat16* Ah = (const __nv_bfloat16*)pAh;
    const __nv_bfloat16* Al = (const __nv_bfloat16*)pAl;
    const __nv_bfloat16* Bh = (const __nv_bfloat16*)pBh;
    const __nv_bfloat16* Bl = (const __nv_bfloat16*)pBl;
#pragma unroll
    for (int ks = 0; ks < 4; ks++) {
        wmma::fragment<wmma::matrix_b, 16, 16, 16, __nv_bfloat16, wmma::col_major> bh[4], bl[4];
#pragma unroll
        for (int ni = 0; ni < 4; ni++) {
            wmma::load_matrix_sync(bh[ni], Bh + (n0 + 16 * ni) * LDA + ks * 16, LDA);
            wmma::load_matrix_sync(bl[ni], Bl + (n0 + 16 * ni) * LDA + ks * 16, LDA);
        }
#pragma unroll
        for (int mi = 0; mi < 4; mi++) {
            wmma::fragment<wmma::matrix_a, 16, 16, 16, __nv_bfloat16, wmma::row_major> ah, al;
            wmma::load_matrix_sync(ah, Ah + (m0 + 16 * mi) * LDA + ks * 16, LDA);
            wmma::load_matrix_sync(al, Al + (m0 + 16 * mi) * LDA + ks * 16, LDA);
#pragma unroll
            for (int ni = 0; ni < 4; ni++) {
                wmma::mma_sync(acc[mi][ni], ah, bh[ni], acc[mi][ni]);
                wmma::mma_sync(acc[mi][ni], ah, bl[ni], acc[mi][ni]);
                wmma::mma_sync(acc[mi][ni], al, bh[ni], acc[mi][ni]);
            }
        }
    }
}

// ---------------- GEMM1: all-copy loader (A rows 256, B rows 128) ----------------
__device__ __forceinline__ void issueG1(const __nv_bfloat16* __restrict__ Bh,
                                        const __nv_bfloat16* __restrict__ Bl,
                                        int K, int rowBase, int M, int colBase,
                                        int kbase, uint32_t sb, int tid) {
#pragma unroll
    for (int i = 0; i < 16; i++) {       // A: 2 halves x 256 rows x 8 k8
        int c = tid + i * 256;
        int half = c >> 11, row = (c >> 3) & 255, k8 = c & 7;
        int gr = rowBase + row;
        int cl = gr < M ? gr : (M - 1);
        int sz = gr < M ? 16 : 0;
        const __nv_bfloat16* src = (half ? g_Al : g_Ah) + (size_t)cl * K + kbase + k8 * 8;
        cpa16(sb + (half ? G1_AL : G1_AH) + row * LDAB + k8 * 16, src, sz);
    }
#pragma unroll
    for (int i = 0; i < 8; i++) {        // B: 2 halves x 128 rows x 8 k8
        int c = tid + i * 256;
        int half = c >> 10, row = (c >> 3) & 127, k8 = c & 7;
        const __nv_bfloat16* src = (half ? Bl : Bh) + (size_t)(colBase + row) * K + kbase + k8 * 8;
        cpa16(sb + (half ? G1_BL : G1_BH) + row * LDAB + k8 * 16, src, 16);
    }
    CPA_COMMIT();
}

__global__ void __launch_bounds__(256)
mgemm1(const __nv_bfloat16* __restrict__ Bh, const __nv_bfloat16* __restrict__ Bl,
       float* __restrict__ C, int M, int K, int Ncols) {
    extern __shared__ char sm[];
    uint32_t sb = (uint32_t)__cvta_generic_to_shared(sm);
    int tid = threadIdx.x;
    int w = tid >> 5;
    int m0 = (w >> 1) * 64, n0 = (w & 1) * 64;
    int rowBase = blockIdx.y * 256;
    int colBase = blockIdx.x * 128;

    wmma::fragment<wmma::accumulator, 16, 16, 16, float> acc[4][4];
#pragma unroll
    for (int mi = 0; mi < 4; mi++)
#pragma unroll
        for (int ni = 0; ni < 4; ni++) wmma::fill_fragment(acc[mi][ni], 0.f);

    int nch = K >> 6;
    issueG1(Bh, Bl, K, rowBase, M, colBase, 0, sb, tid);
    for (int ch = 0; ch < nch; ch++) {
        if (ch + 1 < nch) {
            issueG1(Bh, Bl, K, rowBase, M, colBase, (ch + 1) * 64,
                    sb + ((ch + 1) & 1) * G1_SET, tid);
            CPA_WAIT1();
        } else {
            CPA_WAIT0();
        }
        __syncthreads();
        const char* bc = sm + (ch & 1) * G1_SET;
        mma_chunk64(bc + G1_AH, bc + G1_AL, bc + G1_BH, bc + G1_BL, m0, n0, acc);
        __syncthreads();
    }

    // epilogue: stage, write C, BN stats
    float* Csm = (float*)sm;
#pragma unroll
    for (int mi = 0; mi < 4; mi++)
#pragma unroll
        for (int ni = 0; ni < 4; ni++)
            wmma::store_matrix_sync(Csm + (m0 + 16 * mi) * LDC + n0 + 16 * ni,
                                    acc[mi][ni], LDC, wmma::mem_row_major);
    __syncthreads();
    {
        int grow = rowBase + tid;
        if (grow < M) {
            float* dst = C + (size_t)grow * Ncols + colBase;
            const float* srcr = Csm + tid * LDC;
#pragma unroll
            for (int j = 0; j < 128; j += 4)
                *(float4*)(dst + j) = *(const float4*)(srcr + j);
        }
    }
    {
        int c = tid & 127;
        int r0 = (tid >> 7) * 128;
        float s = 0.f, q = 0.f;
#pragma unroll 4
        for (int r = r0; r < r0 + 128; r++) {
            float v = Csm[r * LDC + c];
            s += v; q += v * v;
        }
        atomicAdd(&g_bnstat[colBase + c], s);
        atomicAdd(&g_bnstat[H4 + colBase + c], q);
    }
}

// ---------------- GEMM2: staged fp32 A -> BN+SELU+split convert ----------------
__device__ __forceinline__ void issueA2(const float* __restrict__ A, int K,
                                        int rowBase, int M, int kbase,
                                        uint32_t sb, int tid) {
#pragma unroll
    for (int i = 0; i < 16; i++) {       // 256 rows x 16 float4
        int c = tid + i * 256;
        int row = c >> 4, j = c & 15;
        int gr = rowBase + row;
        int cl = gr < M ? gr : (M - 1);
        int sz = gr < M ? 16 : 0;
        cpa16(sb + G2_STG + row * 272 + j * 16,
              A + (size_t)cl * K + kbase + j * 4, sz);
    }
}
__device__ __forceinline__ void issueB2(const __nv_bfloat16* __restrict__ Bh,
                                        const __nv_bfloat16* __restrict__ Bl,
                                        int K, int kbase, uint32_t sb, int boff,
                                        int tid) {
#pragma unroll
    for (int i = 0; i < 8; i++) {
        int c = tid + i * 256;
        int half = c >> 10, row = (c >> 3) & 127, k8 = c & 7;
        const __nv_bfloat16* src = (half ? Bl : Bh) + (size_t)row * K + kbase + k8 * 8;
        cpa16(sb + boff + (half ? 18432 : 0) + row * LDAB + k8 * 16, src, 16);
    }
}
// convert stage fp32 -> BN+SELU -> split tiles; thread owns 2 k-cols x 32 rows
__device__ __forceinline__ void convertA(char* sm, int kbase, int tid) {
    int kc = tid & 31;
    int rg = tid >> 5;
    float s0 = g_scale[kbase + 2 * kc],     b0 = g_shift[kbase + 2 * kc];
    float s1 = g_scale[kbase + 2 * kc + 1], b1 = g_shift[kbase + 2 * kc + 1];
    const char* stg = sm + G2_STG;
    char* tah = sm + G2_TAH;
    char* tal = sm + G2_TAL;
#pragma unroll 4
    for (int rr = 0; rr < 32; rr++) {
        int row = rg * 32 + rr;
        float2 v = *(const float2*)(stg + row * 272 + kc * 8);
        float a = selu_f(fmaf(v.x, s0, b0));
        float b = selu_f(fmaf(v.y, s1, b1));
        uint32_t h, l;
        split2(a, b, h, l);
        *(uint32_t*)(tah + row * LDAB + kc * 4) = h;
        *(uint32_t*)(tal + row * LDAB + kc * 4) = l;
    }
}

__global__ void __launch_bounds__(256)
mgemm2(const float* __restrict__ A,
       const __nv_bfloat16* __restrict__ Bh, const __nv_bfloat16* __restrict__ Bl,
       float* __restrict__ C, int M, int K, int Ncols, const float* __restrict__ bias) {
    extern __shared__ char sm[];
    uint32_t sb = (uint32_t)__cvta_generic_to_shared(sm);
    int tid = threadIdx.x;
    int w = tid >> 5;
    int m0 = (w >> 1) * 64, n0 = (w & 1) * 64;
    int rowBase = blockIdx.y * 256;

    wmma::fragment<wmma::accumulator, 16, 16, 16, float> acc[4][4];
#pragma unroll
    for (int mi = 0; mi < 4; mi++)
#pragma unroll
        for (int ni = 0; ni < 4; ni++) wmma::fill_fragment(acc[mi][ni], 0.f);

    int nch = K >> 6;   // 8
    issueA2(A, K, rowBase, M, 0, sb, tid);
    issueB2(Bh, Bl, K, 0, sb, G2_B0, tid);
    CPA_COMMIT();
    CPA_WAIT0();
    __syncthreads();
    convertA(sm, 0, tid);
    __syncthreads();

    for (int ch = 0; ch < nch; ch++) {
        if (ch + 1 < nch) {
            issueA2(A, K, rowBase, M, (ch + 1) * 64, sb, tid);
            issueB2(Bh, Bl, K, (ch + 1) * 64, sb, ((ch + 1) & 1) ? G2_B1 : G2_B0, tid);
            CPA_COMMIT();
        }
        const char* bb = sm + ((ch & 1) ? G2_B1 : G2_B0);
        mma_chunk64(sm + G2_TAH, sm + G2_TAL, bb, bb + 18432, m0, n0, acc);
        if (ch + 1 < nch) {
            CPA_WAIT0();
            __syncthreads();
            convertA(sm, (ch + 1) * 64, tid);
        }
        __syncthreads();
    }

    // epilogue: write C + bias
    float* Csm = (float*)sm;
#pragma unroll
    for (int mi = 0; mi < 4; mi++)
#pragma unroll
        for (int ni = 0; ni < 4; ni++)
            wmma::store_matrix_sync(Csm + (m0 + 16 * mi) * LDC + n0 + 16 * ni,
                                    acc[mi][ni], LDC, wmma::mem_row_major);
    __syncthreads();
    {
        int grow = rowBase + tid;
        if (grow < M) {
            float* dst = C + (size_t)grow * Ncols;
            const float* srcr = Csm + tid * LDC;
#pragma unroll
            for (int j = 0; j < 128; j += 4) {
                float4 v = *(const float4*)(srcr + j);
                v.x += __ldg(&bias[j + 0]);
                v.y += __ldg(&bias[j + 1]);
                v.z += __ldg(&bias[j + 2]);
                v.w += __ldg(&bias[j + 3]);
                *(float4*)(dst + j) = v;
            }
        }
    }
}

// ---------------- weight pre-split ----------------
__global__ void presplit_k(const float* __restrict__ W,
                           __nv_bfloat16* __restrict__ Wh,
                           __nv_bfloat16* __restrict__ Wl, int n2) {
    int i = blockIdx.x * blockDim.x + threadIdx.x;
    if (i >= n2) return;
    float2 v = *(const float2*)(W + 2 * i);
    uint32_t h, l;
    split2(v.x, v.y, h, l);
    ((uint32_t*)Wh)[i] = h;
    ((uint32_t*)Wl)[i] = l;
}

// ---------------- tiny utility kernels ----------------
__global__ void zero_f_k(float* p, int n) {
    int i = blockIdx.x * blockDim.x + threadIdx.x;
    if (i < n) p[i] = 0.f;
}
__global__ void zero_i_k(int* p, int n) {
    int i = blockIdx.x * blockDim.x + threadIdx.x;
    if (i < n) p[i] = 0;
}
__global__ void detect_kernel(const void* ei) {
    if (threadIdx.x == 0) {
        const long long* p = (const long long*)ei;
        int ok = 1;
        for (int i = 0; i < 64; i++) {
            long long v = p[i];
            if (v < 0 || v >= (1LL << 31)) ok = 0;
        }
        g_i64 = ok;
    }
}

// ---------------- CSR build ----------------
__global__ void hist_kernel(const void* ei, int E) {
    int e = blockIdx.x * blockDim.x + threadIdx.x;
    if (e < E) atomicAdd(&g_cursor[readIdx(ei, (long long)E + e)], 1);
}
__global__ void scan1_kernel(int n) {
    __shared__ int s[1024];
    int tid = threadIdx.x;
    int i = blockIdx.x * 1024 + tid;
    int v = (i < n) ? g_cursor[i] : 0;
    s[tid] = v;
    __syncthreads();
    for (int off = 1; off < 1024; off <<= 1) {
        int t = 0;
        if (tid >= off) t = s[tid - off];
        __syncthreads();
        s[tid] += t;
        __syncthreads();
    }
    if (i < n) g_rowptr[i + 1] = s[tid];
    if (tid == 1023) g_bsum[blockIdx.x] = s[1023];
}
__global__ void scan2_kernel(int nb) {
    if (threadIdx.x == 0) {
        int run = 0;
        for (int b = 0; b < nb; b++) { g_boff[b] = run; run += g_bsum[b]; }
    }
}
__global__ void scan3_kernel(int n) {
    int i = blockIdx.x * blockDim.x + threadIdx.x;
    if (i < n) g_rowptr[i + 1] += g_boff[i >> 10];
    if (i == 0) g_rowptr[0] = 0;
}
__global__ void scatter_kernel(const void* ei, int E) {
    int e = blockIdx.x * blockDim.x + threadIdx.x;
    if (e >= E) return;
    int d = readIdx(ei, (long long)E + e);
    int slot = g_rowptr[d] + atomicAdd(&g_cursor[d], 1);
    g_colidx[slot] = readIdx(ei, e);
}

// ---------------- graph ranges ----------------
__global__ void gstart_kernel(const void* batch, int n) {
    int g = blockIdx.x * blockDim.x + threadIdx.x;
    if (g > NG) return;
    int lo = 0, hi = n;
    while (lo < hi) {
        int mid = (lo + hi) >> 1;
        if (readIdx(batch, mid) < g) lo = mid + 1; else hi = mid;
    }
    g_gstart[g] = lo;
}
__global__ void invcnt_kernel() {
    int g = threadIdx.x;
    if (g < NG) {
        int c = g_gstart[g + 1] - g_gstart[g];
        g_invcnt[g] = 1.f / fmaxf((float)c, 1.f);
    }
}

// ---------------- GIN aggregation -> split bf16 A ----------------
__global__ void agg_kernel(const float* __restrict__ h, int N) {
    int warp = (blockIdx.x * blockDim.x + threadIdx.x) >> 5;
    int lane = threadIdx.x & 31;
    if (warp >= N) return;
    float4 acc = __ldg((const float4*)(h + (size_t)warp * DH) + lane);
    int s = g_rowptr[warp], e = g_rowptr[warp + 1];
    for (int p = s; p < e; ++p) {
        int nb = g_colidx[p];
        float4 v = __ldg((const float4*)(h + (size_t)nb * DH) + lane);
        acc.x += v.x; acc.y += v.y; acc.z += v.z; acc.w += v.w;
    }
    uint32_t h0, l0, h1, l1;
    split2(acc.x, acc.y, h0, l0);
    split2(acc.z, acc.w, h1, l1);
    ((uint2*)(g_Ah + (size_t)warp * DH))[lane] = make_uint2(h0, h1);
    ((uint2*)(g_Al + (size_t)warp * DH))[lane] = make_uint2(l0, l1);
}

// ---------------- BN finalize ----------------
__global__ void bnfin_kernel(const float* __restrict__ bn_g,
                             const float* __restrict__ bn_b, float fN) {
    int o = blockIdx.x * blockDim.x + threadIdx.x;
    if (o >= H4) return;
    float mu = g_bnstat[o] / fN;
    float var = fmaxf(g_bnstat[H4 + o] / fN - mu * mu, 0.f);
    float rstd = rsqrtf(var + BN_EPS);
    float sc = bn_g[o] * rstd;
    g_scale[o] = sc;
    g_shift[o] = bn_b[o] - mu * sc;
}

// ---------------- GraphNorm ----------------
__global__ void gnorm_kernel(const float* __restrict__ gn_g,
                             const float* __restrict__ gn_b,
                             const float* __restrict__ gn_a) {
    __shared__ float S[4][DH], Q[4][DH];
    int g = blockIdx.x, t = threadIdx.x;
    int f = t & 127, sl = t >> 7;
    int s = g_gstart[g], e = g_gstart[g + 1];
    float sum = 0.f, sq = 0.f;
    for (int r = s + sl; r < e; r += 4) {
        float v = g_z2[(size_t)r * DH + f];
        sum += v; sq += v * v;
    }
    S[sl][f] = sum; Q[sl][f] = sq;
    __syncthreads();
    if (t < DH) {
        float sm = S[0][f] + S[1][f] + S[2][f] + S[3][f];
        float qm = Q[0][f] + Q[1][f] + Q[2][f] + Q[3][f];
        float ic = g_invcnt[g];
        float mu = sm * ic;
        float am = gn_a[f] * mu;
        float var = fmaxf(qm * ic - 2.f * am * mu + am * am, 0.f);
        float rstd = rsqrtf(var + GN_EPS);
        float GS = gn_g[f] * rstd;
        g_GS[g * DH + f] = GS;
        g_GB[g * DH + f] = gn_b[f] - am * GS;
    }
}
__global__ void final_kernel(float* __restrict__ out, int l) {
    __shared__ float S[4][DH];
    int g = blockIdx.x, t = threadIdx.x;
    int f = t & 127, sl = t >> 7;
    int s = g_gstart[g], e = g_gstart[g + 1];
    float GS = g_GS[g * DH + f], GB = g_GB[g * DH + f];
    float acc = 0.f;
    for (int r = s + sl; r < e; r += 4) {
        float val = selu_f(fmaf(g_z2[(size_t)r * DH + f], GS, GB));
        g_h[(size_t)r * DH + f] = val;
        acc += val;
    }
    S[sl][f] = acc;
    __syncthreads();
    if (t < DH)
        out[(size_t)g * H4 + l * DH + f] =
            (S[0][f] + S[1][f] + S[2][f] + S[3][f]) * g_invcnt[g];
}

// ---------------- launch ----------------
extern "C" void kernel_launch(void* const* d_in, const int* in_sizes, int n_in,
                              void* d_out, int out_size) {
    const float* x    = (const float*)d_in[0];
    const float* W1   = (const float*)d_in[1];
    const float* bn_g = (const float*)d_in[2];
    const float* bn_b = (const float*)d_in[3];
    const float* W2   = (const float*)d_in[4];
    const float* b2   = (const float*)d_in[5];
    const float* gn_g = (const float*)d_in[6];
    const float* gn_b = (const float*)d_in[7];
    const float* gn_a = (const float*)d_in[8];
    const void*  ei   = d_in[9];
    const void*  batch= d_in[10];
    int N = in_sizes[0] / DH;
    int E = in_sizes[9] / 2;
    float* out = (float*)d_out;

    float *pz1, *pz2, *ph, *pbn;
    int* pcur;
    __nv_bfloat16 *pW1h, *pW1l, *pW2h, *pW2l;
    cudaGetSymbolAddress((void**)&pz1, g_z1);
    cudaGetSymbolAddress((void**)&pz2, g_z2);
    cudaGetSymbolAddress((void**)&ph,  g_h);
    cudaGetSymbolAddress((void**)&pbn, g_bnstat);
    cudaGetSymbolAddress((void**)&pcur, g_cursor);
    cudaGetSymbolAddress((void**)&pW1h, g_W1h);
    cudaGetSymbolAddress((void**)&pW1l, g_W1l);
    cudaGetSymbolAddress((void**)&pW2h, g_W2h);
    cudaGetSymbolAddress((void**)&pW2l, g_W2l);

    cudaFuncSetAttribute(mgemm1, cudaFuncAttributeMaxDynamicSharedMemorySize, SMEM_G1);
    cudaFuncSetAttribute(mgemm2, cudaFuncAttributeMaxDynamicSharedMemorySize, SMEM_G2);

    detect_kernel<<<1, 32>>>(ei);
    presplit_k<<<512, 256>>>(W1, pW1h, pW1l, 4 * H4 * DH / 2);
    presplit_k<<<512, 256>>>(W2, pW2h, pW2l, 4 * DH * H4 / 2);
    zero_i_k<<<(N + 255) / 256, 256>>>(pcur, N);
    hist_kernel<<<(E + 255) / 256, 256>>>(ei, E);
    int nb = (N + 1023) / 1024;
    scan1_kernel<<<nb, 1024>>>(N);
    scan2_kernel<<<1, 32>>>(nb);
    scan3_kernel<<<(N + 255) / 256, 256>>>(N);
    zero_i_k<<<(N + 255) / 256, 256>>>(pcur, N);
    scatter_kernel<<<(E + 255) / 256, 256>>>(ei, E);
    gstart_kernel<<<2, 256>>>(batch, N);
    invcnt_kernel<<<1, 256>>>();

    int gm = (N + 255) / 256;
    for (int l = 0; l < 4; l++) {
        const float* hin = l ? (const float*)ph : x;
        agg_kernel<<<(N + 7) / 8, 256>>>(hin, N);
        zero_f_k<<<4, 256>>>(pbn, 2 * H4);
        mgemm1<<<dim3(4, gm), 256, SMEM_G1>>>(
            pW1h + (size_t)l * H4 * DH, pW1l + (size_t)l * H4 * DH, pz1, N, DH, H4);
        bnfin_kernel<<<1, 512>>>(bn_g + l * H4, bn_b + l * H4, (float)N);
        mgemm2<<<dim3(1, gm), 256, SMEM_G2>>>(
            pz1, pW2h + (size_t)l * DH * H4, pW2l + (size_t)l * DH * H4,
            pz2, N, H4, DH, b2 + l * DH);
        gnorm_kernel<<<NG, 512>>>(gn_g + l * DH, gn_b + l * DH, gn_a + l * DH);
        final_kernel<<<NG, 512>>>(out, l);
    }
}